// round 9
// baseline (speedup 1.0000x reference)
#include <cuda_runtime.h>
#include <cuda_bf16.h>
#include <cstdint>

#define B_ROWS     524288
#define D_DIM      64
#define TILE       256
#define THREADS    256
#define GRID       148               // 1 block per SM
#define NTILES     (B_ROWS / TILE)   // 2048
#define ROW_STRIDE 68                // pad 64->68 floats: conflict-free LDS.128
#define NSTAGE     3
#define BUF_FLOATS (TILE * ROW_STRIDE)               // 17408 floats = 69632 B
#define SMEM_BYTES (NSTAGE * BUF_FLOATS * 4 + 9000 * 2)   // 226896 B

__device__ float        g_part[GRID];
__device__ unsigned int g_count = 0;   // reset by last block every call

__device__ __forceinline__ void cp_async16(uint32_t saddr, const void* gptr) {
    asm volatile("cp.async.cg.shared.global [%0], [%1], 16;\n"
                 :: "r"(saddr), "l"(gptr) : "memory");
}

__device__ __forceinline__ void stage_tile(float* __restrict__ dst,
                                           const float4* __restrict__ gx,
                                           int tid)
{
    #pragma unroll
    for (int k = 0; k < 16; k++) {
        int f   = k * THREADS + tid;   // float4 index in tile (4096 total)
        int row = f >> 4;
        int c4  = f & 15;
        uint32_t saddr = (uint32_t)__cvta_generic_to_shared(
            dst + row * ROW_STRIDE + c4 * 4);
        cp_async16(saddr, gx + f);
    }
    asm volatile("cp.async.commit_group;\n" ::: "memory");
}

__global__ void __launch_bounds__(THREADS, 1) mcl_main(
    const float* __restrict__ x,
    const int*   __restrict__ labels,   // int32 on device
    const float* __restrict__ lin_w,
    const float* __restrict__ lin_b,
    const float* __restrict__ linear_p,
    const float* __restrict__ bias_p,
    const float* __restrict__ centers,
    float*       __restrict__ out)
{
    extern __shared__ __align__(16) float smem[];
    float*          sx   = smem;                               // NSTAGE * BUF_FLOATS
    __nv_bfloat16*  stab = (__nv_bfloat16*)(smem + NSTAGE * BUF_FLOATS);
    __shared__ __align__(16) float sw[D_DIM];
    __shared__ float warp_acc[THREADS / 32];
    __shared__ bool  s_last;

    const int tid = threadIdx.x;
    const int bid = blockIdx.x;

    // stage tiles bid and bid+GRID right away (2 groups in flight)
    stage_tile(sx,              (const float4*)(x + (size_t)bid          * TILE * D_DIM), tid);
    stage_tile(sx + BUF_FLOATS, (const float4*)(x + (size_t)(bid + GRID) * TILE * D_DIM), tid);

    // tables -> bf16 in shared (one-time, overlapped with tile fills)
    for (int i = tid; i < 3000; i += THREADS) {
        stab[i]        = __float2bfloat16(__ldg(linear_p + i));
        stab[3000 + i] = __float2bfloat16(__ldg(bias_p   + i));
        stab[6000 + i] = __float2bfloat16(__ldg(centers  + i));
    }
    if (tid < D_DIM / 4)
        ((float4*)sw)[tid] = ((const float4*)lin_w)[tid];
    const float lb = __ldg(lin_b);

    float acc = 0.f;
    int buf = 0;

    for (int tile = bid; tile < NTILES; tile += GRID) {
        const int nxt2 = tile + 2 * GRID;
        if (nxt2 < NTILES) {
            int sbuf = buf + 2; if (sbuf >= NSTAGE) sbuf -= NSTAGE;
            stage_tile(sx + sbuf * BUF_FLOATS,
                       (const float4*)(x + (size_t)nxt2 * TILE * D_DIM), tid);
        }

        int lab = __ldg(&labels[tile * TILE + tid]);
        lab = min(max(lab, 0), 999);

        // tile was committed TWO iterations ago -> this wait is (nearly) free
        if (nxt2 < NTILES)
            asm volatile("cp.async.wait_group 2;\n" ::: "memory");
        else
            asm volatile("cp.async.wait_group 0;\n" ::: "memory");
        __syncthreads();

        // one thread per row: conflict-free LDS.128 sweep (stride 68)
        const float4* xr = (const float4*)(sx + buf * BUF_FLOATS + tid * ROW_STRIDE);
        float m = 0.f, s = 0.f, q = 0.f;
        #pragma unroll
        for (int j = 0; j < 16; j++) {
            float4 v = xr[j];
            float4 w = ((const float4*)sw)[j];
            m = fmaf(v.x, w.x, m); m = fmaf(v.y, w.y, m);
            m = fmaf(v.z, w.z, m); m = fmaf(v.w, w.w, m);
            s += (v.x + v.y) + (v.z + v.w);
            q = fmaf(v.x, v.x, q); q = fmaf(v.y, v.y, q);
            q = fmaf(v.z, v.z, q); q = fmaf(v.w, v.w, q);
        }
        m += lb;

        // bf16 table gathers from shared
        const int l3 = lab * 3;
        const float A0 = __bfloat162float(stab[l3 + 0]);
        const float A1 = __bfloat162float(stab[l3 + 1]);
        const float A2 = __bfloat162float(stab[l3 + 2]);
        const float B0 = __bfloat162float(stab[3000 + l3 + 0]);
        const float B1 = __bfloat162float(stab[3000 + l3 + 1]);
        const float B2 = __bfloat162float(stab[3000 + l3 + 2]);
        const float C0 = __bfloat162float(stab[6000 + l3 + 0]);
        const float C1 = __bfloat162float(stab[6000 + l3 + 1]);
        const float C2 = __bfloat162float(stab[6000 + l3 + 2]);

        const float l0 = fmaf(m, A0, B0);
        const float l1 = fmaf(m, A1, B1);
        const float l2 = fmaf(m, A2, B2);
        const float mx = fmaxf(l0, fmaxf(l1, l2));
        const float e0 = __expf(l0 - mx);
        const float e1 = __expf(l1 - mx);
        const float e2 = __expf(l2 - mx);
        const float inv = 1.f / (e0 + e1 + e2);

        const float t0 = C0 * fmaf(64.f, C0, -2.f * s);
        const float t1 = C1 * fmaf(64.f, C1, -2.f * s);
        const float t2 = C2 * fmaf(64.f, C2, -2.f * s);
        acc += q + inv * (e0 * t0 + e1 * t1 + e2 * t2);

        __syncthreads();   // all reads of buf done before it is restaged
        buf += 1; if (buf >= NSTAGE) buf -= NSTAGE;
    }

    // block reduction
    #pragma unroll
    for (int o = 16; o > 0; o >>= 1)
        acc += __shfl_xor_sync(0xffffffffu, acc, o);
    if ((tid & 31) == 0)
        warp_acc[tid >> 5] = acc;
    __syncthreads();
    if (tid == 0) {
        float t = 0.f;
        #pragma unroll
        for (int i = 0; i < THREADS / 32; i++) t += warp_acc[i];
        g_part[bid] = t;
        __threadfence();
        unsigned int old = atomicAdd(&g_count, 1u);
        s_last = (old == GRID - 1);
    }
    __syncthreads();

    // last block finalizes: fixed-order double reduction (deterministic)
    if (s_last && tid < 32) {
        double t = 0.0;
        for (int i = tid; i < GRID; i += 32)
            t += (double)g_part[i];
        #pragma unroll
        for (int o = 16; o > 0; o >>= 1)
            t += __shfl_xor_sync(0xffffffffu, t, o);
        if (tid == 0) {
            out[0] = (float)(t / (double)B_ROWS);
            g_count = 0;   // rearm for next graph replay
        }
    }
}

extern "C" void kernel_launch(void* const* d_in, const int* in_sizes, int n_in,
                              void* d_out, int out_size)
{
    const float* x        = (const float*)d_in[0];
    const int*   labels   = (const int*)d_in[1];
    const float* lin_w    = (const float*)d_in[2];
    const float* lin_b    = (const float*)d_in[3];
    const float* linear_p = (const float*)d_in[4];
    const float* bias_p   = (const float*)d_in[5];
    const float* centers  = (const float*)d_in[6];

    cudaFuncSetAttribute(mcl_main,
                         cudaFuncAttributeMaxDynamicSharedMemorySize, SMEM_BYTES);
    mcl_main<<<GRID, THREADS, SMEM_BYTES>>>(x, labels, lin_w, lin_b,
                                            linear_p, bias_p, centers,
                                            (float*)d_out);
}

// round 10
// speedup vs baseline: 1.0596x; 1.0596x over previous
#include <cuda_runtime.h>
#include <cuda_bf16.h>
#include <cstdint>

#define B_ROWS     524288
#define D_DIM      64
#define TILE       256
#define THREADS    256
#define GRID       148               // 1 block per SM
#define NTILES     (B_ROWS / TILE)   // 2048
#define NSTAGE     3
#define TILE_BYTES (TILE * D_DIM * 4)            // 65536
#define BUF_FLOATS (TILE * D_DIM)                // 16384, contiguous (TMA bulk)
#define SMEM_BYTES (NSTAGE * TILE_BYTES + 9000 * 2)   // 214608 B

__device__ float        g_part[GRID];
__device__ unsigned int g_count = 0;   // reset by last block every call

__device__ __forceinline__ void mbar_wait(uint32_t mbar, uint32_t parity) {
    uint32_t done;
    asm volatile(
        "{\n\t.reg .pred p;\n\t"
        "mbarrier.try_wait.parity.acquire.cta.shared::cta.b64 p, [%1], %2;\n\t"
        "selp.b32 %0, 1, 0, p;\n\t}"
        : "=r"(done) : "r"(mbar), "r"(parity) : "memory");
    if (!done) {
        asm volatile(
            "{\n\t.reg .pred P1;\n\t"
            "WL_%=:\n\t"
            "mbarrier.try_wait.parity.acquire.cta.shared::cta.b64 P1, [%0], %1, 0x989680;\n\t"
            "@P1 bra.uni WD_%=;\n\t"
            "bra.uni WL_%=;\n\t"
            "WD_%=:\n\t}"
            :: "r"(mbar), "r"(parity) : "memory");
    }
}

__device__ __forceinline__ void bulk_copy(uint32_t dst_smem, const void* src,
                                          uint32_t bytes, uint32_t mbar) {
    asm volatile("mbarrier.arrive.expect_tx.shared.b64 _, [%0], %1;"
                 :: "r"(mbar), "r"(bytes) : "memory");
    asm volatile(
        "cp.async.bulk.shared::cluster.global.mbarrier::complete_tx::bytes "
        "[%0], [%1], %2, [%3];"
        :: "r"(dst_smem), "l"(src), "r"(bytes), "r"(mbar) : "memory");
}

__global__ void __launch_bounds__(THREADS, 1) mcl_main(
    const float* __restrict__ x,
    const int*   __restrict__ labels,   // int32 on device
    const float* __restrict__ lin_w,
    const float* __restrict__ lin_b,
    const float* __restrict__ linear_p,
    const float* __restrict__ bias_p,
    const float* __restrict__ centers,
    float*       __restrict__ out)
{
    extern __shared__ __align__(128) float smem[];
    float*         sx   = smem;                                  // 3 * 64KB tiles
    __nv_bfloat16* stab = (__nv_bfloat16*)(smem + NSTAGE * BUF_FLOATS);
    __shared__ __align__(16) float sw[D_DIM];
    __shared__ __align__(8) unsigned long long mbar[NSTAGE];
    __shared__ float warp_acc[THREADS / 32];
    __shared__ bool  s_last;

    const int tid = threadIdx.x;
    const int bid = blockIdx.x;
    const uint32_t smem_u32 = (uint32_t)__cvta_generic_to_shared(smem);
    const uint32_t mbar_u32 = (uint32_t)__cvta_generic_to_shared(mbar);

    if (tid == 0) {
        #pragma unroll
        for (int i = 0; i < NSTAGE; i++)
            asm volatile("mbarrier.init.shared.b64 [%0], 1;"
                         :: "r"(mbar_u32 + 8 * i) : "memory");
    }
    __syncthreads();

    // prologue: bulk-stage tiles bid and bid+GRID (one UBLKCP each)
    if (tid == 0) {
        bulk_copy(smem_u32,              x + (size_t)bid          * BUF_FLOATS,
                  TILE_BYTES, mbar_u32);
        bulk_copy(smem_u32 + TILE_BYTES, x + (size_t)(bid + GRID) * BUF_FLOATS,
                  TILE_BYTES, mbar_u32 + 8);
    }

    // tables -> bf16 in shared (overlapped with TMA fills)
    for (int i = tid; i < 3000; i += THREADS) {
        stab[i]        = __float2bfloat16(__ldg(linear_p + i));
        stab[3000 + i] = __float2bfloat16(__ldg(bias_p   + i));
        stab[6000 + i] = __float2bfloat16(__ldg(centers  + i));
    }
    if (tid < D_DIM / 4)
        ((float4*)sw)[tid] = ((const float4*)lin_w)[tid];
    const float lb = __ldg(lin_b);

    float acc = 0.f;
    int it = 0;

    for (int tile = bid; tile < NTILES; tile += GRID, ++it) {
        const int s = it % NSTAGE;
        const int nxt2 = tile + 2 * GRID;
        if (nxt2 < NTILES && tid == 0) {
            const int s2 = (it + 2) % NSTAGE;
            bulk_copy(smem_u32 + s2 * TILE_BYTES,
                      x + (size_t)nxt2 * BUF_FLOATS,
                      TILE_BYTES, mbar_u32 + 8 * s2);
        }

        int lab = __ldg(&labels[tile * TILE + tid]);
        lab = min(max(lab, 0), 999);

        mbar_wait(mbar_u32 + 8 * s, (uint32_t)((it / NSTAGE) & 1));

        // one thread per row; rotated quad order keeps LDS.128 conflict-free
        const float4* xr  = (const float4*)(sx + s * BUF_FLOATS) + tid * 16;
        const float4* swq = (const float4*)sw;
        float m = 0.f, ssum = 0.f, q = 0.f;
        #pragma unroll
        for (int j = 0; j < 16; j++) {
            const int qi = (j + tid) & 15;
            float4 v = xr[qi];
            float4 w = swq[qi];
            m = fmaf(v.x, w.x, m); m = fmaf(v.y, w.y, m);
            m = fmaf(v.z, w.z, m); m = fmaf(v.w, w.w, m);
            ssum += (v.x + v.y) + (v.z + v.w);
            q = fmaf(v.x, v.x, q); q = fmaf(v.y, v.y, q);
            q = fmaf(v.z, v.z, q); q = fmaf(v.w, v.w, q);
        }
        m += lb;

        const int l3 = lab * 3;
        const float A0 = __bfloat162float(stab[l3 + 0]);
        const float A1 = __bfloat162float(stab[l3 + 1]);
        const float A2 = __bfloat162float(stab[l3 + 2]);
        const float B0 = __bfloat162float(stab[3000 + l3 + 0]);
        const float B1 = __bfloat162float(stab[3000 + l3 + 1]);
        const float B2 = __bfloat162float(stab[3000 + l3 + 2]);
        const float C0 = __bfloat162float(stab[6000 + l3 + 0]);
        const float C1 = __bfloat162float(stab[6000 + l3 + 1]);
        const float C2 = __bfloat162float(stab[6000 + l3 + 2]);

        const float l0 = fmaf(m, A0, B0);
        const float l1 = fmaf(m, A1, B1);
        const float l2 = fmaf(m, A2, B2);
        const float mx = fmaxf(l0, fmaxf(l1, l2));
        const float e0 = __expf(l0 - mx);
        const float e1 = __expf(l1 - mx);
        const float e2 = __expf(l2 - mx);
        const float inv = 1.f / (e0 + e1 + e2);

        const float t0 = C0 * fmaf(64.f, C0, -2.f * ssum);
        const float t1 = C1 * fmaf(64.f, C1, -2.f * ssum);
        const float t2 = C2 * fmaf(64.f, C2, -2.f * ssum);
        acc += q + inv * (e0 * t0 + e1 * t1 + e2 * t2);

        __syncthreads();   // all reads of stage s done before it is restaged
    }

    // block reduction
    #pragma unroll
    for (int o = 16; o > 0; o >>= 1)
        acc += __shfl_xor_sync(0xffffffffu, acc, o);
    if ((tid & 31) == 0)
        warp_acc[tid >> 5] = acc;
    __syncthreads();
    if (tid == 0) {
        float t = 0.f;
        #pragma unroll
        for (int i = 0; i < THREADS / 32; i++) t += warp_acc[i];
        g_part[bid] = t;
        __threadfence();
        unsigned int old = atomicAdd(&g_count, 1u);
        s_last = (old == GRID - 1);
    }
    __syncthreads();

    // last block finalizes: fixed-order double reduction (deterministic)
    if (s_last && tid < 32) {
        double t = 0.0;
        for (int i = tid; i < GRID; i += 32)
            t += (double)g_part[i];
        #pragma unroll
        for (int o = 16; o > 0; o >>= 1)
            t += __shfl_xor_sync(0xffffffffu, t, o);
        if (tid == 0) {
            out[0] = (float)(t / (double)B_ROWS);
            g_count = 0;   // rearm for next graph replay
        }
    }
}

extern "C" void kernel_launch(void* const* d_in, const int* in_sizes, int n_in,
                              void* d_out, int out_size)
{
    const float* x        = (const float*)d_in[0];
    const int*   labels   = (const int*)d_in[1];
    const float* lin_w    = (const float*)d_in[2];
    const float* lin_b    = (const float*)d_in[3];
    const float* linear_p = (const float*)d_in[4];
    const float* bias_p   = (const float*)d_in[5];
    const float* centers  = (const float*)d_in[6];

    cudaFuncSetAttribute(mcl_main,
                         cudaFuncAttributeMaxDynamicSharedMemorySize, SMEM_BYTES);
    mcl_main<<<GRID, THREADS, SMEM_BYTES>>>(x, labels, lin_w, lin_b,
                                            linear_p, bias_p, centers,
                                            (float*)d_out);
}